// round 11
// baseline (speedup 1.0000x reference)
#include <cuda_runtime.h>
#include <cstdint>
#include <math.h>

#define HW 4096
#define NTILES 640
#define NHALF  1280
#define NTOT_F 2621440.0f
#define EPS_V 1e-8f

#define SPARSITY_W 0.8f
#define CONC_W     1.5f
#define COORD_W    1.0f
#define BG_W       0.1f

__device__ float g_tile_contrib[NTILES];
__device__ unsigned int g_done = 0;

__device__ __forceinline__ float fast_tanh(float x) {
    float r;
    asm("tanh.approx.f32 %0, %1;" : "=f"(r) : "f"(x));
    return r;
}

__device__ __forceinline__ unsigned int smem_u32(const void* p) {
    unsigned int a;
    asm("{ .reg .u64 t; cvta.to.shared.u64 t, %1; cvt.u32.u64 %0, t; }"
        : "=r"(a) : "l"(p));
    return a;
}

__device__ __forceinline__ void st_peer_f32(unsigned int local_addr, int rank, float v) {
    asm volatile(
        "{ .reg .b32 r; mapa.shared::cluster.u32 r, %0, %1; "
        "st.shared::cluster.f32 [r], %2; }"
        :: "r"(local_addr), "r"(rank), "f"(v) : "memory");
}

// One CTA per HALF tile (32 rows): 128 threads, 16 px/thread, 8 LDG.128
// front-issued. Clusters of 2 = one tile; pair combine via DSMEM.
__global__ __cluster_dims__(2, 1, 1) __launch_bounds__(128, 9)
void loss_kernel(const float4* __restrict__ pred,
                 const float4* __restrict__ tgt,
                 float* __restrict__ out) {
    __shared__ float warp_red[4][10];
    __shared__ float peer[10];          // rank 1 writes here in rank 0's CTA

    const int hidx = blockIdx.x;        // [0,1280)
    const int tile = hidx >> 1;
    unsigned int rank;
    asm("mov.u32 %0, %%cluster_ctarank;" : "=r"(rank));
    const int half = hidx & 1;          // == rank for this launch geometry

    const size_t base = (size_t)tile * (HW / 4) + (size_t)half * 512;
    const float4* __restrict__ P = pred + base;
    const float4* __restrict__ T = tgt  + base;

    const int tid  = threadIdx.x;       // [0,128)
    const int lane = tid & 31;
    const int wid  = tid >> 5;          // [0,4)

    // elem j (in tile) = half*2048 + 4*(tid + 128k) + c, k=0..3:
    //   col = ((4*tid)&63) + c  (k-invariant);  row = 32*half + (tid>>4) + 8k
    const float c0f = (float)((tid * 4) & 63);
    const float y0f = (float)((tid >> 4) + 32 * half);

    // front-load: 8 LDG.128 in flight
    float4 X[4], Tv4[4];
    #pragma unroll
    for (int k = 0; k < 4; k++) X[k]   = P[tid + 128 * k];
    #pragma unroll
    for (int k = 0; k < 4; k++) Tv4[k] = T[tid + 128 * k];

    float S = 0.f, Ts = 0.f;
    float wxp = 0.f, wyp = 0.f, wxt = 0.f, wyt = 0.f;
    float foc = 0.f, bg = 0.f, plog = 0.f, mxh2 = -1.f;

    #pragma unroll
    for (int k = 0; k < 4; k++) {
        float xv[4] = {X[k].x,   X[k].y,   X[k].z,   X[k].w};
        float tv[4] = {Tv4[k].x, Tv4[k].y, Tv4[k].z, Tv4[k].w};
        float pv[4];
        #pragma unroll
        for (int c = 0; c < 4; c++) {
            float x  = xv[c];
            float t  = tv[c];
            float h2 = fast_tanh(0.5f * x);          // 2p-1
            float p  = fmaf(0.5f, h2, 0.5f);
            pv[c] = p;
            float pm = fmaf(0.5f, fabsf(h2), 0.5f);  // sigmoid(|x|)
            float lp = __logf(pm);                   // -lp = log1p(e^{-|x|})
            float bce = fmaf(-x, t, fmaxf(x, 0.f) - lp);
            float om  = fabsf(t - p);                // 1 - p_t (t in {0,1})
            float om2 = om * om;
            foc  = fmaf(om2, bce, foc);
            bg   = fmaf(om2, 1.f - t, bg);           // p^2 when t==0
            plog = fmaf(p, fminf(x, 0.f) + lp, plog);
            mxh2 = fmaxf(mxh2, h2);
        }
        const float kf = (float)k;
        float gs = (pv[0] + pv[1]) + (pv[2] + pv[3]);
        float gw = fmaf(3.f, pv[3], fmaf(2.f, pv[2], pv[1]));
        S   += gs;
        wxp += gw;
        wyp  = fmaf(kf, gs, wyp);
        float gt = (tv[0] + tv[1]) + (tv[2] + tv[3]);
        float gu = fmaf(3.f, tv[3], fmaf(2.f, tv[2], tv[1]));
        Ts  += gt;
        wxt += gu;
        wyt  = fmaf(kf, gt, wyt);
    }

    float pxs = fmaf(c0f, S,  wxp);
    float pys = fmaf(y0f, S,  8.f * wyp);    // rows step by 8 per k
    float txs = fmaf(c0f, Ts, wxt);
    float tys = fmaf(y0f, Ts, 8.f * wyt);
    float mx  = fmaf(0.5f, mxh2, 0.5f);

    // warp butterfly: 9 sums + 1 max
    const unsigned FULL = 0xffffffffu;
    #pragma unroll
    for (int o = 16; o; o >>= 1) {
        S    += __shfl_xor_sync(FULL, S,    o);
        Ts   += __shfl_xor_sync(FULL, Ts,   o);
        pxs  += __shfl_xor_sync(FULL, pxs,  o);
        pys  += __shfl_xor_sync(FULL, pys,  o);
        txs  += __shfl_xor_sync(FULL, txs,  o);
        tys  += __shfl_xor_sync(FULL, tys,  o);
        foc  += __shfl_xor_sync(FULL, foc,  o);
        bg   += __shfl_xor_sync(FULL, bg,   o);
        plog += __shfl_xor_sync(FULL, plog, o);
        mx    = fmaxf(mx, __shfl_xor_sync(FULL, mx, o));
    }
    if (lane == 0) {
        warp_red[wid][0] = S;    warp_red[wid][1] = Ts;
        warp_red[wid][2] = pxs;  warp_red[wid][3] = pys;
        warp_red[wid][4] = txs;  warp_red[wid][5] = tys;
        warp_red[wid][6] = foc;  warp_red[wid][7] = bg;
        warp_red[wid][8] = plog; warp_red[wid][9] = mx;
    }
    __syncthreads();

    // warp 0: cross-warp combine (4 lanes hold the 4 warp rows)
    float a[10];
    if (wid == 0) {
        if (lane < 4) {
            #pragma unroll
            for (int i = 0; i < 10; i++) a[i] = warp_red[lane][i];
        } else {
            #pragma unroll
            for (int i = 0; i < 10; i++) a[i] = 0.f;
        }
        #pragma unroll
        for (int o = 2; o; o >>= 1) {
            #pragma unroll
            for (int i = 0; i < 9; i++) a[i] += __shfl_xor_sync(FULL, a[i], o);
            a[9] = fmaxf(a[9], __shfl_xor_sync(FULL, a[9], o));
        }
        // rank 1 ships its half's stats into rank 0's smem
        if (rank == 1 && lane == 0) {
            unsigned int pa = smem_u32(peer);
            #pragma unroll
            for (int i = 0; i < 10; i++)
                st_peer_f32(pa + 4u * i, 0, a[i]);
        }
    }

    // cluster barrier (release/acquire): peer[] visible to rank 0 after wait
    asm volatile("barrier.cluster.arrive.aligned;" ::: "memory");
    asm volatile("barrier.cluster.wait.aligned;"   ::: "memory");

    if (rank != 0 || wid != 0) return;

    unsigned int prev = 0;
    if (lane == 0) {
        // combine halves (commutative -> deterministic) and finalize
        #pragma unroll
        for (int i = 0; i < 9; i++) a[i] += peer[i];
        a[9] = fmaxf(a[9], peer[9]);

        float Sp  = a[0] + EPS_V;
        float inv = 1.f / Sp;
        float ent = inv * (a[0] * logf(Sp) - a[8]);
        float ts  = a[1] + EPS_V;
        float px  = a[2] * inv, py = a[3] * inv;
        float tx  = a[4] / ts,  ty = a[5] / ts;
        float dx  = px - tx,    dy = py - ty;
        float coord = sqrtf(dx * dx + dy * dy);
        float conc  = 1.f - a[9];

        g_tile_contrib[tile] =
            (a[6] + BG_W * a[7]) * (1.f / NTOT_F) +
            (SPARSITY_W * ent + CONC_W * conc + COORD_W * coord) * (1.f / (float)NTILES);

        asm volatile("atom.add.acq_rel.gpu.u32 %0, [%1], 1;"
                     : "=r"(prev) : "l"(&g_done) : "memory");
    }
    prev = __shfl_sync(FULL, prev, 0);

    if (prev == NTILES - 1) {
        // last tile-finalizer: warp 0 reduces all 640 contributions (fixed order)
        float v = 0.f;
        #pragma unroll
        for (int i = 0; i < 20; i++)            // 640 / 32
            v += g_tile_contrib[lane + 32 * i];
        #pragma unroll
        for (int o = 16; o; o >>= 1)
            v += __shfl_xor_sync(FULL, v, o);
        if (lane == 0) {
            out[0] = v;
            g_done = 0;   // reset for next graph replay
        }
    }
}

extern "C" void kernel_launch(void* const* d_in, const int* in_sizes, int n_in,
                              void* d_out, int out_size) {
    const float4* pred = (const float4*)d_in[0];
    const float4* tgt  = (const float4*)d_in[1];
    float* out = (float*)d_out;
    loss_kernel<<<NHALF, 128>>>(pred, tgt, out);
}

// round 12
// speedup vs baseline: 1.1463x; 1.1463x over previous
#include <cuda_runtime.h>
#include <cstdint>
#include <math.h>

#define HW 4096
#define NTILES 640
#define NTOT_F 2621440.0f
#define EPS_V 1e-8f
#define LN2F 0.69314718055994530942f

#define SPARSITY_W 0.8f
#define CONC_W     1.5f
#define COORD_W    1.0f
#define BG_W       0.1f

__device__ float g_tile_contrib[NTILES];
__device__ unsigned int g_done = 0;

__device__ __forceinline__ float fast_tanh(float x) {
    float r;
    asm("tanh.approx.f32 %0, %1;" : "=f"(r) : "f"(x));
    return r;
}
__device__ __forceinline__ float fast_lg2(float x) {
    float r;
    asm("lg2.approx.f32 %0, %1;" : "=f"(r) : "f"(x));
    return r;
}

// One CTA per tile: 128 threads, 32 px/thread (16 front-issued LDG.128).
// Log terms accumulated in log2 domain; ln2 applied once per tile.
__global__ __launch_bounds__(128, 5)
void loss_kernel(const float4* __restrict__ pred,
                 const float4* __restrict__ tgt,
                 float* __restrict__ out) {
    __shared__ float warp_red[4][12];
    __shared__ bool is_last;

    const int tile = blockIdx.x;
    const float4* __restrict__ P = pred + (size_t)tile * (HW / 4);
    const float4* __restrict__ T = tgt  + (size_t)tile * (HW / 4);

    const int tid  = threadIdx.x;          // [0,128)
    const int lane = tid & 31;
    const int wid  = tid >> 5;             // [0,4)

    // elem j = 4*(tid + 128k) + c, k=0..7:
    //   col = ((4*tid)&63) + c  (k-invariant);  row = (tid>>4) + 8k
    const float c0f = (float)((tid * 4) & 63);
    const float y0f = (float)(tid >> 4);

    // front-load everything: 16 x LDG.128 in flight
    float4 X[8], Tv4[8];
    #pragma unroll
    for (int k = 0; k < 8; k++) X[k]   = P[tid + 128 * k];
    #pragma unroll
    for (int k = 0; k < 8; k++) Tv4[k] = T[tid + 128 * k];

    float S = 0.f, Ts = 0.f;
    float wxp = 0.f, wyp = 0.f, wxt = 0.f, wyt = 0.f;
    float focA = 0.f, foc2 = 0.f, bg = 0.f;
    float plogA = 0.f, plg2 = 0.f, mxh2 = -1.f;

    #pragma unroll
    for (int k = 0; k < 8; k++) {
        float xv[4] = {X[k].x,   X[k].y,   X[k].z,   X[k].w};
        float tv[4] = {Tv4[k].x, Tv4[k].y, Tv4[k].z, Tv4[k].w};
        float pv[4];
        #pragma unroll
        for (int c = 0; c < 4; c++) {
            float x  = xv[c];
            float t  = tv[c];
            float h2 = fast_tanh(0.5f * x);          // 2p-1
            float p  = fmaf(0.5f, h2, 0.5f);
            pv[c] = p;
            float pm  = fmaf(0.5f, fabsf(h2), 0.5f); // sigmoid(|x|)
            float l2p = fast_lg2(pm);                // log2(sigmoid(|x|)) <= 0
            // bce = max(x,0) - x*t - ln2*l2p  (split into A + log2 parts)
            float bceA = fmaf(-x, t, fmaxf(x, 0.f));
            float om   = fabsf(t - p);               // 1 - p_t (t in {0,1})
            float om2  = om * om;
            focA = fmaf(om2, bceA, focA);
            foc2 = fmaf(om2, l2p,  foc2);
            bg   = fmaf(om2, 1.f - t, bg);           // p^2 when t==0
            // log p = min(x,0) + ln2*l2p
            plogA = fmaf(p, fminf(x, 0.f), plogA);
            plg2  = fmaf(p, l2p, plg2);
            mxh2  = fmaxf(mxh2, h2);
        }
        const float kf = (float)k;
        float gs = (pv[0] + pv[1]) + (pv[2] + pv[3]);
        float gw = fmaf(3.f, pv[3], fmaf(2.f, pv[2], pv[1]));
        S   += gs;
        wxp += gw;
        wyp  = fmaf(kf, gs, wyp);
        float gt = (tv[0] + tv[1]) + (tv[2] + tv[3]);
        float gu = fmaf(3.f, tv[3], fmaf(2.f, tv[2], tv[1]));
        Ts  += gt;
        wxt += gu;
        wyt  = fmaf(kf, gt, wyt);
    }

    float pxs = fmaf(c0f, S,  wxp);
    float pys = fmaf(y0f, S,  8.f * wyp);    // rows step by 8 per k
    float txs = fmaf(c0f, Ts, wxt);
    float tys = fmaf(y0f, Ts, 8.f * wyt);
    float mx  = fmaf(0.5f, mxh2, 0.5f);

    // warp butterfly: 11 sums + 1 max
    const unsigned FULL = 0xffffffffu;
    #pragma unroll
    for (int o = 16; o; o >>= 1) {
        S     += __shfl_xor_sync(FULL, S,     o);
        Ts    += __shfl_xor_sync(FULL, Ts,    o);
        pxs   += __shfl_xor_sync(FULL, pxs,   o);
        pys   += __shfl_xor_sync(FULL, pys,   o);
        txs   += __shfl_xor_sync(FULL, txs,   o);
        tys   += __shfl_xor_sync(FULL, tys,   o);
        focA  += __shfl_xor_sync(FULL, focA,  o);
        foc2  += __shfl_xor_sync(FULL, foc2,  o);
        bg    += __shfl_xor_sync(FULL, bg,    o);
        plogA += __shfl_xor_sync(FULL, plogA, o);
        plg2  += __shfl_xor_sync(FULL, plg2,  o);
        mx     = fmaxf(mx, __shfl_xor_sync(FULL, mx, o));
    }
    if (lane == 0) {
        warp_red[wid][0]  = S;     warp_red[wid][1]  = Ts;
        warp_red[wid][2]  = pxs;   warp_red[wid][3]  = pys;
        warp_red[wid][4]  = txs;   warp_red[wid][5]  = tys;
        warp_red[wid][6]  = focA;  warp_red[wid][7]  = foc2;
        warp_red[wid][8]  = bg;    warp_red[wid][9]  = plogA;
        warp_red[wid][10] = plg2;  warp_red[wid][11] = mx;
    }
    __syncthreads();

    // cross-warp combine: 4 lanes of warp 0
    if (wid == 0 && lane < 4) {
        float a[12];
        #pragma unroll
        for (int i = 0; i < 12; i++) a[i] = warp_red[lane][i];
        const unsigned M4 = 0x0000000fu;
        #pragma unroll
        for (int o = 2; o; o >>= 1) {
            #pragma unroll
            for (int i = 0; i < 11; i++) a[i] += __shfl_xor_sync(M4, a[i], o);
            a[11] = fmaxf(a[11], __shfl_xor_sync(M4, a[11], o));
        }
        if (lane == 0) {
            float foc  = fmaf(-LN2F, a[7],  a[6]);   // focA - ln2*foc2
            float plog = fmaf( LN2F, a[10], a[9]);   // plogA + ln2*plg2

            float Sp  = a[0] + EPS_V;
            float inv = 1.f / Sp;
            float ent = inv * (a[0] * logf(Sp) - plog);
            float ts  = a[1] + EPS_V;
            float px  = a[2] * inv, py = a[3] * inv;
            float tx  = a[4] / ts,  ty = a[5] / ts;
            float dx  = px - tx,    dy = py - ty;
            float coord = sqrtf(dx * dx + dy * dy);
            float conc  = 1.f - a[11];

            g_tile_contrib[tile] =
                (foc + BG_W * a[8]) * (1.f / NTOT_F) +
                (SPARSITY_W * ent + CONC_W * conc + COORD_W * coord) * (1.f / (float)NTILES);

            __threadfence();
            unsigned r = atomicAdd(&g_done, 1u);
            is_last = (r == NTILES - 1);
        }
    }
    __syncthreads();

    if (is_last) {
        __threadfence();
        float v = 0.f;
        #pragma unroll
        for (int i = 0; i < 5; i++)                // 640 / 128
            v += g_tile_contrib[tid + 128 * i];
        #pragma unroll
        for (int o = 16; o; o >>= 1)
            v += __shfl_xor_sync(FULL, v, o);
        if (lane == 0) warp_red[wid][0] = v;
        __syncthreads();
        if (tid == 0) {
            float s = (warp_red[0][0] + warp_red[1][0])
                    + (warp_red[2][0] + warp_red[3][0]);
            out[0] = s;
            g_done = 0;   // reset for graph replay
        }
    }
}

extern "C" void kernel_launch(void* const* d_in, const int* in_sizes, int n_in,
                              void* d_out, int out_size) {
    const float4* pred = (const float4*)d_in[0];
    const float4* tgt  = (const float4*)d_in[1];
    float* out = (float*)d_out;
    loss_kernel<<<NTILES, 128>>>(pred, tgt, out);
}